// round 13
// baseline (speedup 1.0000x reference)
#include <cuda_runtime.h>
#include <math.h>

// ---------------------------------------------------------------------------
// PGA(3,0,1) blade algebra, computed at compile time.
// Blade order: 0:() 1:e0 2:e1 3:e2 4:e3 5:e01 6:e02 7:e03 8:e12 9:e13 10:e23
//              11:e012 12:e013 13:e023 14:e123 15:e0123
// ---------------------------------------------------------------------------

__host__ __device__ constexpr int pc4(int x) {
    return ((x >> 0) & 1) + ((x >> 1) & 1) + ((x >> 2) & 1) + ((x >> 3) & 1);
}

__host__ __device__ constexpr int I2M(int i) {
    return (i == 0) ? 0  : (i == 1) ? 1  : (i == 2) ? 2  : (i == 3) ? 4  :
           (i == 4) ? 8  : (i == 5) ? 3  : (i == 6) ? 5  : (i == 7) ? 9  :
           (i == 8) ? 6  : (i == 9) ? 10 : (i == 10) ? 12 : (i == 11) ? 7 :
           (i == 12) ? 11 : (i == 13) ? 13 : (i == 14) ? 14 : 15;
}

__host__ __device__ constexpr int M2I(int m) {
    return (m == 0) ? 0  : (m == 1) ? 1  : (m == 2) ? 2  : (m == 3) ? 5  :
           (m == 4) ? 3  : (m == 5) ? 6  : (m == 6) ? 8  : (m == 7) ? 11 :
           (m == 8) ? 4  : (m == 9) ? 7  : (m == 10) ? 9 : (m == 11) ? 12 :
           (m == 12) ? 10 : (m == 13) ? 13 : (m == 14) ? 14 : 15;
}

__host__ __device__ constexpr int msign(int a, int b) {
    int s = 0;
    if ((b >> 0) & 1) s += pc4(a >> 1);
    if ((b >> 1) & 1) s += pc4(a >> 2);
    if ((b >> 2) & 1) s += pc4(a >> 3);
    return (s & 1) ? -1 : 1;
}

__host__ __device__ constexpr int dsign(int m) { return msign(m, 15 ^ m); }

__host__ __device__ constexpr int jsign(int ma, int mb) {
    return dsign(ma) * dsign(mb) * msign(15 ^ ma, 15 ^ mb) * dsign(ma & mb);
}

// ---------------------------------------------------------------------------
// Compile-time unroll driver (all indices constexpr -> literal subscripts).
// ---------------------------------------------------------------------------
template<int I> struct IC { static constexpr int v = I; };

template<int N> struct Unroll {
    template<typename F>
    __device__ __forceinline__ static void run(F&& f) {
        Unroll<N - 1>::run(f);
        f(IC<N - 1>{});
    }
};
template<> struct Unroll<0> {
    template<typename F>
    __device__ __forceinline__ static void run(F&&) {}
};

// ---------------------------------------------------------------------------
// Branch-free Phi(x) via Abramowitz-Stegun 7.1.26 erf (max abs err 1.5e-7).
// ---------------------------------------------------------------------------
__device__ __forceinline__ float phi_cdf(float x) {
    const float z  = fabsf(x) * 0.70710678118654752f;   // |x|/sqrt(2)
    const float t  = __frcp_rn(fmaf(0.3275911f, z, 1.0f));
    float p = fmaf(1.061405429f, t, -1.453152027f);
    p = fmaf(p, t,  1.421413741f);
    p = fmaf(p, t, -0.284496736f);
    p = fmaf(p, t,  0.254829592f);
    p = p * t;
    const float e   = __expf(-z * z);                   // MUFU EX2 path
    const float erf = 1.0f - p * e;
    const float se  = copysignf(erf, x);
    return fmaf(0.5f, se, 0.5f);
}

// ---------------------------------------------------------------------------
// One thread per token; 256 threads / block; coalesced global I/O staged
// through a swizzled smem buffer.
//
// Gate-deferred formulation: the GELU gate G is a scalar factor of the whole
// bilinear, so the bilinear runs UNGATED on raw x with the raw (token-
// independent) w1/v1 weights:
//   u'_j = w1[g]*x_j + v1[g]*x_src   (j>0),    u'_0 = w10*x0 + b1*nrm
//   gp_ref = G * rinv^2 * gp_raw,   join_ref = G * x15 * rinv^3 * jn_raw
// -> the rsqrt/rcp/exp gate chain runs CONCURRENTLY with the 273-FMA
// bilinear; G enters only via the 18 output-weight scalars.
// ---------------------------------------------------------------------------
#define TPB 256

__device__ __forceinline__ int swz(int t, int c) {
    return 4 * t + (c ^ ((t >> 1) & 3));
}

template<bool FULL>
__global__ void __launch_bounds__(TPB)
mvffn_kernel(const float* __restrict__ x,
             const float* __restrict__ w1, const float* __restrict__ v1, const float* __restrict__ b1,
             const float* __restrict__ wg, const float* __restrict__ vg, const float* __restrict__ bg,
             const float* __restrict__ wj, const float* __restrict__ vj, const float* __restrict__ bj,
             float* __restrict__ out, int ntok)
{
    __shared__ float4 stage[TPB * 4];

    const int tid  = threadIdx.x;
    const int base = blockIdx.x * TPB;
    const float4* xin4 = reinterpret_cast<const float4*>(x)  + (size_t)base * 4;
    float4*       out4 = reinterpret_cast<float4*>(out)      + (size_t)base * 4;
    const int     nf4  = FULL ? TPB * 4 : min(TPB, ntok - base) * 4;

    // ---- coalesced load -> swizzled smem ----
    #pragma unroll
    for (int k = 0; k < 4; k++) {
        int f = tid + k * TPB;
        if (FULL || f < nf4) stage[swz(f >> 2, f & 3)] = xin4[f];
    }
    __syncthreads();

    if (FULL || base + tid < ntok) {
        float4 q0 = stage[swz(tid, 0)], q1 = stage[swz(tid, 1)];
        float4 q2 = stage[swz(tid, 2)], q3 = stage[swz(tid, 3)];

        // RAW x — also the residual.
        float xn[16] = { q0.x, q0.y, q0.z, q0.w,
                         q1.x, q1.y, q1.z, q1.w,
                         q2.x, q2.y, q2.z, q2.w,
                         q3.x, q3.y, q3.z, q3.w };

        // ---- norm sum (tree-reduced) over idx 0,2,3,4,8,9,10,14 ----
        float sa = fmaf(xn[0],  xn[0],  1e-5f);
        sa       = fmaf(xn[2],  xn[2],  sa);
        float sb = xn[3] * xn[3];
        sb       = fmaf(xn[4],  xn[4],  sb);
        float sc = xn[8] * xn[8];
        sc       = fmaf(xn[9],  xn[9],  sc);
        float sd = xn[10] * xn[10];
        sd       = fmaf(xn[14], xn[14], sd);
        const float s = (sa + sb) + (sc + sd);

        const float rinv  = rsqrtf(s);
        const float rinv2 = rinv * rinv;
        const float nrm   = s * rinv;            // sqrt(s)

        // ---- raw first-linear weights (token-independent) ----
        const float4 w1a = *reinterpret_cast<const float4*>(w1);
        const float  w1e = w1[4];
        const float4 v1a = *reinterpret_cast<const float4*>(v1);
        const float W1r[5] = { w1a.x, w1a.y, w1a.z, w1a.w, w1e };
        const float V1r[4] = { v1a.x, v1a.y, v1a.z, v1a.w };

        // gate chain — independent of the bilinear below (runs concurrently)
        const float xp0 = fmaf(w1a.x, xn[0] * rinv, b1[0]);
        const float G   = xp0 * phi_cdf(xp0);

        // ungated bias column (homogenized): u'_0 = w10*x0 + b1*nrm
        const float u0 = fmaf(w1a.x, xn[0], b1[0] * nrm);

        // ---- UNGATED bilinear on RAW x, all indices constexpr ----
        float gp[16], jn[16];
        Unroll<16>::run([&](auto K) {
            constexpr int k = decltype(K)::v;
            gp[k] = 0.f; jn[k] = 0.f;
        });

        Unroll<16>::run([&](auto J) {
            constexpr int j  = decltype(J)::v;
            constexpr int mb = I2M(j);
            constexpr int gB = pc4(mb);

            float uj;
            if constexpr (j == 0) {
                uj = u0;
            } else {
                uj = W1r[gB] * xn[j];
                if constexpr ((mb & 1) && gB < 4)
                    uj = fmaf(V1r[gB], xn[M2I(mb ^ 1)], uj);
            }

            Unroll<16>::run([&](auto I_) {
                constexpr int i  = decltype(I_)::v;
                constexpr int ma = I2M(i);
                if constexpr (!(ma & mb & 1)) {            // e0^2 = 0
                    constexpr int k = M2I(ma ^ mb);
                    if constexpr (msign(ma, mb) > 0) gp[k] = fmaf(xn[i],  uj, gp[k]);
                    else                             gp[k] = fmaf(xn[i], -uj, gp[k]);
                }
                if constexpr ((ma | mb) == 15) {           // join support
                    constexpr int k = M2I(ma & mb);
                    if constexpr (jsign(ma, mb) > 0) jn[k] = fmaf(xn[i],  uj, jn[k]);
                    else                             jn[k] = fmaf(xn[i], -uj, jn[k]);
                }
            });
        });

        // ---- output linears; gate + normalization folded into weights ----
        const float4 wga = *reinterpret_cast<const float4*>(wg);
        const float  wge = wg[4];
        const float4 vga = *reinterpret_cast<const float4*>(vg);
        const float4 wja = *reinterpret_cast<const float4*>(wj);
        const float  wje = wj[4];
        const float4 vja = *reinterpret_cast<const float4*>(vj);

        const float gfac = G * rinv2;                    // gp path
        const float jfac = (G * xn[15]) * (rinv2 * rinv); // join path

        const float WG[5] = { wga.x * gfac, wga.y * gfac, wga.z * gfac,
                              wga.w * gfac, wge * gfac };
        const float VG[4] = { vga.x * gfac, vga.y * gfac, vga.z * gfac,
                              vga.w * gfac };
        const float WJ[5] = { wja.x * jfac, wja.y * jfac, wja.z * jfac,
                              wja.w * jfac, wje * jfac };
        const float VJ[4] = { vja.x * jfac, vja.y * jfac, vja.z * jfac,
                              vja.w * jfac };

        float o[16];
        Unroll<16>::run([&](auto D) {
            constexpr int d = decltype(D)::v;
            constexpr int m = I2M(d);
            constexpr int g = pc4(m);
            float v = fmaf(WG[g], gp[d], xn[d]);   // residual = raw x[d]
            v = fmaf(WJ[g], jn[d], v);
            if constexpr ((m & 1) && g < 4) {
                constexpr int sidx = M2I(m ^ 1);
                v = fmaf(VG[g], gp[sidx], v);
                v = fmaf(VJ[g], jn[sidx], v);
            }
            o[d] = v;
        });
        o[0] += bg[0] + bj[0];

        stage[swz(tid, 0)] = make_float4(o[0],  o[1],  o[2],  o[3]);
        stage[swz(tid, 1)] = make_float4(o[4],  o[5],  o[6],  o[7]);
        stage[swz(tid, 2)] = make_float4(o[8],  o[9],  o[10], o[11]);
        stage[swz(tid, 3)] = make_float4(o[12], o[13], o[14], o[15]);
    }
    __syncthreads();

    // ---- coalesced store from swizzled smem ----
    #pragma unroll
    for (int k = 0; k < 4; k++) {
        int f = tid + k * TPB;
        if (FULL || f < nf4) out4[f] = stage[swz(f >> 2, f & 3)];
    }
}

extern "C" void kernel_launch(void* const* d_in, const int* in_sizes, int n_in,
                              void* d_out, int out_size)
{
    const float* x  = (const float*)d_in[0];
    const float* w1 = (const float*)d_in[1];
    const float* v1 = (const float*)d_in[2];
    const float* b1 = (const float*)d_in[3];
    const float* wg = (const float*)d_in[4];
    const float* vg = (const float*)d_in[5];
    const float* bg = (const float*)d_in[6];
    const float* wj = (const float*)d_in[7];
    const float* vj = (const float*)d_in[8];
    const float* bj = (const float*)d_in[9];

    const int ntok   = in_sizes[0] / 16;
    const int blocks = (ntok + TPB - 1) / TPB;

    if (ntok % TPB == 0)
        mvffn_kernel<true><<<blocks, TPB>>>(x, w1, v1, b1, wg, vg, bg, wj, vj, bj,
                                            (float*)d_out, ntok);
    else
        mvffn_kernel<false><<<blocks, TPB>>>(x, w1, v1, b1, wg, vg, bg, wj, vj, bj,
                                             (float*)d_out, ntok);
}

// round 14
// speedup vs baseline: 1.2843x; 1.2843x over previous
#include <cuda_runtime.h>
#include <math.h>

// ---------------------------------------------------------------------------
// PGA(3,0,1) blade algebra, computed at compile time.
// Blade order: 0:() 1:e0 2:e1 3:e2 4:e3 5:e01 6:e02 7:e03 8:e12 9:e13 10:e23
//              11:e012 12:e013 13:e023 14:e123 15:e0123
// ---------------------------------------------------------------------------

__host__ __device__ constexpr int pc4(int x) {
    return ((x >> 0) & 1) + ((x >> 1) & 1) + ((x >> 2) & 1) + ((x >> 3) & 1);
}

__host__ __device__ constexpr int I2M(int i) {
    return (i == 0) ? 0  : (i == 1) ? 1  : (i == 2) ? 2  : (i == 3) ? 4  :
           (i == 4) ? 8  : (i == 5) ? 3  : (i == 6) ? 5  : (i == 7) ? 9  :
           (i == 8) ? 6  : (i == 9) ? 10 : (i == 10) ? 12 : (i == 11) ? 7 :
           (i == 12) ? 11 : (i == 13) ? 13 : (i == 14) ? 14 : 15;
}

__host__ __device__ constexpr int M2I(int m) {
    return (m == 0) ? 0  : (m == 1) ? 1  : (m == 2) ? 2  : (m == 3) ? 5  :
           (m == 4) ? 3  : (m == 5) ? 6  : (m == 6) ? 8  : (m == 7) ? 11 :
           (m == 8) ? 4  : (m == 9) ? 7  : (m == 10) ? 9 : (m == 11) ? 12 :
           (m == 12) ? 10 : (m == 13) ? 13 : (m == 14) ? 14 : 15;
}

__host__ __device__ constexpr int msign(int a, int b) {
    int s = 0;
    if ((b >> 0) & 1) s += pc4(a >> 1);
    if ((b >> 1) & 1) s += pc4(a >> 2);
    if ((b >> 2) & 1) s += pc4(a >> 3);
    return (s & 1) ? -1 : 1;
}

__host__ __device__ constexpr int dsign(int m) { return msign(m, 15 ^ m); }

__host__ __device__ constexpr int jsign(int ma, int mb) {
    return dsign(ma) * dsign(mb) * msign(15 ^ ma, 15 ^ mb) * dsign(ma & mb);
}

// ---------------------------------------------------------------------------
// Compile-time unroll driver (all indices constexpr -> literal subscripts).
// ---------------------------------------------------------------------------
template<int I> struct IC { static constexpr int v = I; };

template<int N> struct Unroll {
    template<typename F>
    __device__ __forceinline__ static void run(F&& f) {
        Unroll<N - 1>::run(f);
        f(IC<N - 1>{});
    }
};
template<> struct Unroll<0> {
    template<typename F>
    __device__ __forceinline__ static void run(F&&) {}
};

// ---------------------------------------------------------------------------
// Branch-free Phi(x) via Abramowitz-Stegun 7.1.26 erf (max abs err 1.5e-7).
// ---------------------------------------------------------------------------
__device__ __forceinline__ float phi_cdf(float x) {
    const float z  = fabsf(x) * 0.70710678118654752f;   // |x|/sqrt(2)
    const float t  = __frcp_rn(fmaf(0.3275911f, z, 1.0f));
    float p = fmaf(1.061405429f, t, -1.453152027f);
    p = fmaf(p, t,  1.421413741f);
    p = fmaf(p, t, -0.284496736f);
    p = fmaf(p, t,  0.254829592f);
    p = p * t;
    const float e   = __expf(-z * z);                   // MUFU EX2 path
    const float erf = 1.0f - p * e;
    const float se  = copysignf(erf, x);
    return fmaf(0.5f, se, 0.5f);
}

// ---------------------------------------------------------------------------
// One thread per token; 256 threads / block; coalesced global I/O staged
// through a swizzled smem buffer. Bilinear on RAW x, normalization folded
// into output-weight scalars; gate folded into first-linear weights
// (R12 champion formulation). FULL=true drops bounds checks.
// ---------------------------------------------------------------------------
#define TPB 256

__device__ __forceinline__ int swz(int t, int c) {
    return 4 * t + (c ^ ((t >> 1) & 3));
}

template<bool FULL>
__global__ void __launch_bounds__(TPB)
mvffn_kernel(const float* __restrict__ x,
             const float* __restrict__ w1, const float* __restrict__ v1, const float* __restrict__ b1,
             const float* __restrict__ wg, const float* __restrict__ vg, const float* __restrict__ bg,
             const float* __restrict__ wj, const float* __restrict__ vj, const float* __restrict__ bj,
             float* __restrict__ out, int ntok)
{
    __shared__ float4 stage[TPB * 4];

    const int tid  = threadIdx.x;
    const int base = blockIdx.x * TPB;
    const float4* xin4 = reinterpret_cast<const float4*>(x)  + (size_t)base * 4;
    float4*       out4 = reinterpret_cast<float4*>(out)      + (size_t)base * 4;
    const int     nf4  = FULL ? TPB * 4 : min(TPB, ntok - base) * 4;

    // ---- weight loads issued early: overlap the staging barrier ----
    const float4 w1a = *reinterpret_cast<const float4*>(w1);
    const float  w1e = w1[4];
    const float4 v1a = *reinterpret_cast<const float4*>(v1);
    const float  b1s = b1[0];
    const float4 wga = *reinterpret_cast<const float4*>(wg);
    const float  wge = wg[4];
    const float4 vga = *reinterpret_cast<const float4*>(vg);
    const float4 wja = *reinterpret_cast<const float4*>(wj);
    const float  wje = wj[4];
    const float4 vja = *reinterpret_cast<const float4*>(vj);
    const float  bsum = bg[0] + bj[0];

    // ---- coalesced load -> swizzled smem ----
    #pragma unroll
    for (int k = 0; k < 4; k++) {
        int f = tid + k * TPB;
        if (FULL || f < nf4) stage[swz(f >> 2, f & 3)] = xin4[f];
    }
    __syncthreads();

    if (FULL || base + tid < ntok) {
        float4 q0 = stage[swz(tid, 0)], q1 = stage[swz(tid, 1)];
        float4 q2 = stage[swz(tid, 2)], q3 = stage[swz(tid, 3)];

        // RAW x — also the residual.
        float xn[16] = { q0.x, q0.y, q0.z, q0.w,
                         q1.x, q1.y, q1.z, q1.w,
                         q2.x, q2.y, q2.z, q2.w,
                         q3.x, q3.y, q3.z, q3.w };

        // ---- norm sum (tree-reduced) over idx 0,2,3,4,8,9,10,14 ----
        float sa = fmaf(xn[0],  xn[0],  1e-5f);
        sa       = fmaf(xn[2],  xn[2],  sa);
        float sb = xn[3] * xn[3];
        sb       = fmaf(xn[4],  xn[4],  sb);
        float sc = xn[8] * xn[8];
        sc       = fmaf(xn[9],  xn[9],  sc);
        float sd = xn[10] * xn[10];
        sd       = fmaf(xn[14], xn[14], sd);
        const float s = (sa + sb) + (sc + sd);

        const float rinv  = rsqrtf(s);
        const float rinv2 = rinv * rinv;
        const float rinv3 = rinv2 * rinv;
        const float nrm   = s * rinv;            // sqrt(s)

        // ---- gate: xp0 = w1[0]*xn_norm[0] + b1; G = exact-accuracy GELU ----
        const float xp0 = fmaf(w1a.x, xn[0] * rinv, b1s);
        const float G   = xp0 * phi_cdf(xp0);

        const float W1f[5] = { G * w1a.x, G * w1a.y, G * w1a.z, G * w1a.w, G * w1e };
        const float V1f[4] = { G * v1a.x, G * v1a.y, G * v1a.z, G * v1a.w };
        const float u0 = (G * xp0) * nrm;        // homogenize the bias column

        // ---- bilinear on RAW x, all indices constexpr ----
        float gp[16], jn[16];
        Unroll<16>::run([&](auto K) {
            constexpr int k = decltype(K)::v;
            gp[k] = 0.f; jn[k] = 0.f;
        });

        Unroll<16>::run([&](auto J) {
            constexpr int j  = decltype(J)::v;
            constexpr int mb = I2M(j);
            constexpr int gB = pc4(mb);

            float uj;
            if constexpr (j == 0) {
                uj = u0;
            } else {
                uj = W1f[gB] * xn[j];
                if constexpr ((mb & 1) && gB < 4)
                    uj = fmaf(V1f[gB], xn[M2I(mb ^ 1)], uj);
            }

            Unroll<16>::run([&](auto I_) {
                constexpr int i  = decltype(I_)::v;
                constexpr int ma = I2M(i);
                if constexpr (!(ma & mb & 1)) {            // e0^2 = 0
                    constexpr int k = M2I(ma ^ mb);
                    if constexpr (msign(ma, mb) > 0) gp[k] = fmaf(xn[i],  uj, gp[k]);
                    else                             gp[k] = fmaf(xn[i], -uj, gp[k]);
                }
                if constexpr ((ma | mb) == 15) {           // join support
                    constexpr int k = M2I(ma & mb);
                    if constexpr (jsign(ma, mb) > 0) jn[k] = fmaf(xn[i],  uj, jn[k]);
                    else                             jn[k] = fmaf(xn[i], -uj, jn[k]);
                }
            });
        });

        // ---- output linears with normalization folded into the weights ----
        const float gfac = rinv2;                 // gp path scale
        const float jfac = xn[15] * rinv3;        // join path scale

        const float WG[5] = { wga.x * gfac, wga.y * gfac, wga.z * gfac,
                              wga.w * gfac, wge * gfac };
        const float VG[4] = { vga.x * gfac, vga.y * gfac, vga.z * gfac,
                              vga.w * gfac };
        const float WJ[5] = { wja.x * jfac, wja.y * jfac, wja.z * jfac,
                              wja.w * jfac, wje * jfac };
        const float VJ[4] = { vja.x * jfac, vja.y * jfac, vja.z * jfac,
                              vja.w * jfac };

        float o[16];
        Unroll<16>::run([&](auto D) {
            constexpr int d = decltype(D)::v;
            constexpr int m = I2M(d);
            constexpr int g = pc4(m);
            float v = fmaf(WG[g], gp[d], xn[d]);   // residual = raw x[d]
            v = fmaf(WJ[g], jn[d], v);
            if constexpr ((m & 1) && g < 4) {
                constexpr int sidx = M2I(m ^ 1);
                v = fmaf(VG[g], gp[sidx], v);
                v = fmaf(VJ[g], jn[sidx], v);
            }
            o[d] = v;
        });
        o[0] += bsum;

        stage[swz(tid, 0)] = make_float4(o[0],  o[1],  o[2],  o[3]);
        stage[swz(tid, 1)] = make_float4(o[4],  o[5],  o[6],  o[7]);
        stage[swz(tid, 2)] = make_float4(o[8],  o[9],  o[10], o[11]);
        stage[swz(tid, 3)] = make_float4(o[12], o[13], o[14], o[15]);
    }
    __syncthreads();

    // ---- coalesced store from swizzled smem ----
    #pragma unroll
    for (int k = 0; k < 4; k++) {
        int f = tid + k * TPB;
        if (FULL || f < nf4) out4[f] = stage[swz(f >> 2, f & 3)];
    }
}

extern "C" void kernel_launch(void* const* d_in, const int* in_sizes, int n_in,
                              void* d_out, int out_size)
{
    const float* x  = (const float*)d_in[0];
    const float* w1 = (const float*)d_in[1];
    const float* v1 = (const float*)d_in[2];
    const float* b1 = (const float*)d_in[3];
    const float* wg = (const float*)d_in[4];
    const float* vg = (const float*)d_in[5];
    const float* bg = (const float*)d_in[6];
    const float* wj = (const float*)d_in[7];
    const float* vj = (const float*)d_in[8];
    const float* bj = (const float*)d_in[9];

    const int ntok   = in_sizes[0] / 16;
    const int blocks = (ntok + TPB - 1) / TPB;

    if (ntok % TPB == 0)
        mvffn_kernel<true><<<blocks, TPB>>>(x, w1, v1, b1, wg, vg, bg, wj, vj, bj,
                                            (float*)d_out, ntok);
    else
        mvffn_kernel<false><<<blocks, TPB>>>(x, w1, v1, b1, wg, vg, bg, wj, vj, bj,
                                             (float*)d_out, ntok);
}

// round 15
// speedup vs baseline: 1.3100x; 1.0200x over previous
#include <cuda_runtime.h>
#include <math.h>

// ---------------------------------------------------------------------------
// PGA(3,0,1) blade algebra, computed at compile time.
// Blade order: 0:() 1:e0 2:e1 3:e2 4:e3 5:e01 6:e02 7:e03 8:e12 9:e13 10:e23
//              11:e012 12:e013 13:e023 14:e123 15:e0123
// ---------------------------------------------------------------------------

__host__ __device__ constexpr int pc4(int x) {
    return ((x >> 0) & 1) + ((x >> 1) & 1) + ((x >> 2) & 1) + ((x >> 3) & 1);
}

__host__ __device__ constexpr int I2M(int i) {
    return (i == 0) ? 0  : (i == 1) ? 1  : (i == 2) ? 2  : (i == 3) ? 4  :
           (i == 4) ? 8  : (i == 5) ? 3  : (i == 6) ? 5  : (i == 7) ? 9  :
           (i == 8) ? 6  : (i == 9) ? 10 : (i == 10) ? 12 : (i == 11) ? 7 :
           (i == 12) ? 11 : (i == 13) ? 13 : (i == 14) ? 14 : 15;
}

__host__ __device__ constexpr int M2I(int m) {
    return (m == 0) ? 0  : (m == 1) ? 1  : (m == 2) ? 2  : (m == 3) ? 5  :
           (m == 4) ? 3  : (m == 5) ? 6  : (m == 6) ? 8  : (m == 7) ? 11 :
           (m == 8) ? 4  : (m == 9) ? 7  : (m == 10) ? 9 : (m == 11) ? 12 :
           (m == 12) ? 10 : (m == 13) ? 13 : (m == 14) ? 14 : 15;
}

__host__ __device__ constexpr int msign(int a, int b) {
    int s = 0;
    if ((b >> 0) & 1) s += pc4(a >> 1);
    if ((b >> 1) & 1) s += pc4(a >> 2);
    if ((b >> 2) & 1) s += pc4(a >> 3);
    return (s & 1) ? -1 : 1;
}

__host__ __device__ constexpr int dsign(int m) { return msign(m, 15 ^ m); }

__host__ __device__ constexpr int jsign(int ma, int mb) {
    return dsign(ma) * dsign(mb) * msign(15 ^ ma, 15 ^ mb) * dsign(ma & mb);
}

// ---------------------------------------------------------------------------
// Compile-time unroll driver (all indices constexpr -> literal subscripts).
// ---------------------------------------------------------------------------
template<int I> struct IC { static constexpr int v = I; };

template<int N> struct Unroll {
    template<typename F>
    __device__ __forceinline__ static void run(F&& f) {
        Unroll<N - 1>::run(f);
        f(IC<N - 1>{});
    }
};
template<> struct Unroll<0> {
    template<typename F>
    __device__ __forceinline__ static void run(F&&) {}
};

// ---------------------------------------------------------------------------
// Branch-free Phi(x) via Abramowitz-Stegun 7.1.26 erf (max abs err 1.5e-7).
// ---------------------------------------------------------------------------
__device__ __forceinline__ float phi_cdf(float x) {
    const float z  = fabsf(x) * 0.70710678118654752f;   // |x|/sqrt(2)
    const float t  = __frcp_rn(fmaf(0.3275911f, z, 1.0f));
    float p = fmaf(1.061405429f, t, -1.453152027f);
    p = fmaf(p, t,  1.421413741f);
    p = fmaf(p, t, -0.284496736f);
    p = fmaf(p, t,  0.254829592f);
    p = p * t;
    const float e   = __expf(-z * z);                   // MUFU EX2 path
    const float erf = 1.0f - p * e;
    const float se  = copysignf(erf, x);
    return fmaf(0.5f, se, 0.5f);
}

// ---------------------------------------------------------------------------
// One thread per token, direct LDG.128/STG.128 I/O (no smem staging: memory
// is far from binding and the staging machinery cost ~90 issued inst + two
// barriers per thread). R12 math: bilinear on RAW x, normalization folded
// into output-weight scalars, gate folded into first-linear weights,
// branch-free erf, tree-reduced norm. FULL=true drops all bounds checks.
// ---------------------------------------------------------------------------
#define TPB 256

template<bool FULL>
__global__ void __launch_bounds__(TPB)
mvffn_kernel(const float* __restrict__ x,
             const float* __restrict__ w1, const float* __restrict__ v1, const float* __restrict__ b1,
             const float* __restrict__ wg, const float* __restrict__ vg, const float* __restrict__ bg,
             const float* __restrict__ wj, const float* __restrict__ vj, const float* __restrict__ bj,
             float* __restrict__ out, int ntok)
{
    const int t = blockIdx.x * TPB + threadIdx.x;
    if (!FULL && t >= ntok) return;

    // ---- weight loads issued first (overlap with token loads) ----
    const float4 w1a = *reinterpret_cast<const float4*>(w1);
    const float  w1e = w1[4];
    const float4 v1a = *reinterpret_cast<const float4*>(v1);
    const float  b1s = b1[0];
    const float4 wga = *reinterpret_cast<const float4*>(wg);
    const float  wge = wg[4];
    const float4 vga = *reinterpret_cast<const float4*>(vg);
    const float4 wja = *reinterpret_cast<const float4*>(wj);
    const float  wje = wj[4];
    const float4 vja = *reinterpret_cast<const float4*>(vj);
    const float  bsum = bg[0] + bj[0];

    const float4* xin4 = reinterpret_cast<const float4*>(x) + (size_t)t * 4;
    float4 q0 = xin4[0], q1 = xin4[1], q2 = xin4[2], q3 = xin4[3];

    // RAW x — also the residual.
    float xn[16] = { q0.x, q0.y, q0.z, q0.w,
                     q1.x, q1.y, q1.z, q1.w,
                     q2.x, q2.y, q2.z, q2.w,
                     q3.x, q3.y, q3.z, q3.w };

    // ---- norm sum (tree-reduced) over idx 0,2,3,4,8,9,10,14 ----
    float sa = fmaf(xn[0],  xn[0],  1e-5f);
    sa       = fmaf(xn[2],  xn[2],  sa);
    float sb = xn[3] * xn[3];
    sb       = fmaf(xn[4],  xn[4],  sb);
    float sc = xn[8] * xn[8];
    sc       = fmaf(xn[9],  xn[9],  sc);
    float sd = xn[10] * xn[10];
    sd       = fmaf(xn[14], xn[14], sd);
    const float s = (sa + sb) + (sc + sd);

    const float rinv  = rsqrtf(s);
    const float rinv2 = rinv * rinv;
    const float rinv3 = rinv2 * rinv;
    const float nrm   = s * rinv;            // sqrt(s)

    // ---- gate: xp0 = w1[0]*xn_norm[0] + b1; G = exact-accuracy GELU ----
    const float xp0 = fmaf(w1a.x, xn[0] * rinv, b1s);
    const float G   = xp0 * phi_cdf(xp0);

    const float W1f[5] = { G * w1a.x, G * w1a.y, G * w1a.z, G * w1a.w, G * w1e };
    const float V1f[4] = { G * v1a.x, G * v1a.y, G * v1a.z, G * v1a.w };
    const float u0 = (G * xp0) * nrm;        // homogenize the bias column

    // ---- bilinear on RAW x, all indices constexpr ----
    float gp[16], jn[16];
    Unroll<16>::run([&](auto K) {
        constexpr int k = decltype(K)::v;
        gp[k] = 0.f; jn[k] = 0.f;
    });

    Unroll<16>::run([&](auto J) {
        constexpr int j  = decltype(J)::v;
        constexpr int mb = I2M(j);
        constexpr int gB = pc4(mb);

        float uj;
        if constexpr (j == 0) {
            uj = u0;
        } else {
            uj = W1f[gB] * xn[j];
            if constexpr ((mb & 1) && gB < 4)
                uj = fmaf(V1f[gB], xn[M2I(mb ^ 1)], uj);
        }

        Unroll<16>::run([&](auto I_) {
            constexpr int i  = decltype(I_)::v;
            constexpr int ma = I2M(i);
            if constexpr (!(ma & mb & 1)) {            // e0^2 = 0
                constexpr int k = M2I(ma ^ mb);
                if constexpr (msign(ma, mb) > 0) gp[k] = fmaf(xn[i],  uj, gp[k]);
                else                             gp[k] = fmaf(xn[i], -uj, gp[k]);
            }
            if constexpr ((ma | mb) == 15) {           // join support
                constexpr int k = M2I(ma & mb);
                if constexpr (jsign(ma, mb) > 0) jn[k] = fmaf(xn[i],  uj, jn[k]);
                else                             jn[k] = fmaf(xn[i], -uj, jn[k]);
            }
        });
    });

    // ---- output linears with normalization folded into the weights ----
    const float gfac = rinv2;                 // gp path scale
    const float jfac = xn[15] * rinv3;        // join path scale

    const float WG[5] = { wga.x * gfac, wga.y * gfac, wga.z * gfac,
                          wga.w * gfac, wge * gfac };
    const float VG[4] = { vga.x * gfac, vga.y * gfac, vga.z * gfac,
                          vga.w * gfac };
    const float WJ[5] = { wja.x * jfac, wja.y * jfac, wja.z * jfac,
                          wja.w * jfac, wje * jfac };
    const float VJ[4] = { vja.x * jfac, vja.y * jfac, vja.z * jfac,
                          vja.w * jfac };

    float o[16];
    Unroll<16>::run([&](auto D) {
        constexpr int d = decltype(D)::v;
        constexpr int m = I2M(d);
        constexpr int g = pc4(m);
        float v = fmaf(WG[g], gp[d], xn[d]);   // residual = raw x[d]
        v = fmaf(WJ[g], jn[d], v);
        if constexpr ((m & 1) && g < 4) {
            constexpr int sidx = M2I(m ^ 1);
            v = fmaf(VG[g], gp[sidx], v);
            v = fmaf(VJ[g], jn[sidx], v);
        }
        o[d] = v;
    });
    o[0] += bsum;

    float4* op = reinterpret_cast<float4*>(out) + (size_t)t * 4;
    op[0] = make_float4(o[0],  o[1],  o[2],  o[3]);
    op[1] = make_float4(o[4],  o[5],  o[6],  o[7]);
    op[2] = make_float4(o[8],  o[9],  o[10], o[11]);
    op[3] = make_float4(o[12], o[13], o[14], o[15]);
}

extern "C" void kernel_launch(void* const* d_in, const int* in_sizes, int n_in,
                              void* d_out, int out_size)
{
    const float* x  = (const float*)d_in[0];
    const float* w1 = (const float*)d_in[1];
    const float* v1 = (const float*)d_in[2];
    const float* b1 = (const float*)d_in[3];
    const float* wg = (const float*)d_in[4];
    const float* vg = (const float*)d_in[5];
    const float* bg = (const float*)d_in[6];
    const float* wj = (const float*)d_in[7];
    const float* vj = (const float*)d_in[8];
    const float* bj = (const float*)d_in[9];

    const int ntok   = in_sizes[0] / 16;
    const int blocks = (ntok + TPB - 1) / TPB;

    if (ntok % TPB == 0)
        mvffn_kernel<true><<<blocks, TPB>>>(x, w1, v1, b1, wg, vg, bg, wj, vj, bj,
                                            (float*)d_out, ntok);
    else
        mvffn_kernel<false><<<blocks, TPB>>>(x, w1, v1, b1, wg, vg, bg, wj, vj, bj,
                                             (float*)d_out, ntok);
}